// round 3
// baseline (speedup 1.0000x reference)
#include <cuda_runtime.h>
#include <math.h>

// Problem constants
#define BQ 256
#define DQ 511
#define HQ 5120
#define SPLITK 16
#define KCHUNK (HQ / SPLITK)   // 320

// Scratch (allocation-free rule: __device__ globals)
__device__ float g_h[BQ * HQ];                 // [256, 5120] hidden (post-ReLU)
__device__ float g_part[SPLITK * BQ * DQ];     // split-K partials
__device__ float g_phi[BQ * DQ];               // [256, 511]
__device__ float g_quad[BQ];                   // [256]

// ---------------------------------------------------------------------------
// GEMM1: g_h = relu(theta12[256,511] @ W1[5120,511]^T + b1)   (NT gemm)
// Tile: BM=64, BN=128, BK=16; 256 threads; 4x8 per-thread register tile.
// ---------------------------------------------------------------------------
__global__ __launch_bounds__(256, 2)
void gemm1_relu(const float* __restrict__ A, const float* __restrict__ W,
                const float* __restrict__ bias) {
    __shared__ float As[16][68];
    __shared__ float Bs[16][132];
    const int m0 = blockIdx.y * 64;
    const int n0 = blockIdx.x * 128;
    const int tid = threadIdx.x;
    const int lk = tid & 15, lr = tid >> 4;   // loader layout 16(k) x 16(row)
    const int tx = tid & 15, ty = tid >> 4;   // compute layout 16(n) x 16(m)

    float acc[4][8];
#pragma unroll
    for (int i = 0; i < 4; ++i)
#pragma unroll
        for (int j = 0; j < 8; ++j) acc[i][j] = 0.f;

    for (int k0 = 0; k0 < DQ; k0 += 16) {
        const int k = k0 + lk;
        const bool kin = (k < DQ);
#pragma unroll
        for (int i = 0; i < 4; ++i)
            As[lk][lr + i * 16] = kin ? A[(m0 + lr + i * 16) * DQ + k] : 0.f;
#pragma unroll
        for (int i = 0; i < 8; ++i)
            Bs[lk][lr + i * 16] = kin ? W[(n0 + lr + i * 16) * DQ + k] : 0.f;
        __syncthreads();
#pragma unroll
        for (int kk = 0; kk < 16; ++kk) {
            float a[4], b[8];
#pragma unroll
            for (int i = 0; i < 4; ++i) a[i] = As[kk][ty * 4 + i];
#pragma unroll
            for (int j = 0; j < 8; ++j) b[j] = Bs[kk][tx * 8 + j];
#pragma unroll
            for (int i = 0; i < 4; ++i)
#pragma unroll
                for (int j = 0; j < 8; ++j)
                    acc[i][j] = fmaf(a[i], b[j], acc[i][j]);
        }
        __syncthreads();
    }

#pragma unroll
    for (int i = 0; i < 4; ++i) {
        const int m = m0 + ty * 4 + i;
#pragma unroll
        for (int j = 0; j < 8; ++j) {
            const int n = n0 + tx * 8 + j;
            float v = acc[i][j] + bias[n];
            g_h[m * HQ + n] = v > 0.f ? v : 0.f;
        }
    }
}

// ---------------------------------------------------------------------------
// GEMM2 (split-K): g_part[s] += h[256,5120] @ W2[511,5120]^T over K-chunk s.
// Same tiling; N=511 needs bounds.
// ---------------------------------------------------------------------------
__global__ __launch_bounds__(256, 2)
void gemm2_split(const float* __restrict__ W2) {
    __shared__ float As[16][68];
    __shared__ float Bs[16][132];
    const int m0 = blockIdx.y * 64;
    const int n0 = blockIdx.x * 128;
    const int s  = blockIdx.z;
    const int tid = threadIdx.x;
    const int lk = tid & 15, lr = tid >> 4;
    const int tx = tid & 15, ty = tid >> 4;

    float acc[4][8];
#pragma unroll
    for (int i = 0; i < 4; ++i)
#pragma unroll
        for (int j = 0; j < 8; ++j) acc[i][j] = 0.f;

    const int kend = (s + 1) * KCHUNK;
    for (int k0 = s * KCHUNK; k0 < kend; k0 += 16) {
        const int k = k0 + lk;
#pragma unroll
        for (int i = 0; i < 4; ++i)
            As[lk][lr + i * 16] = g_h[(m0 + lr + i * 16) * HQ + k];
#pragma unroll
        for (int i = 0; i < 8; ++i) {
            const int n = n0 + lr + i * 16;
            Bs[lk][lr + i * 16] = (n < DQ) ? W2[n * HQ + k] : 0.f;
        }
        __syncthreads();
#pragma unroll
        for (int kk = 0; kk < 16; ++kk) {
            float a[4], b[8];
#pragma unroll
            for (int i = 0; i < 4; ++i) a[i] = As[kk][ty * 4 + i];
#pragma unroll
            for (int j = 0; j < 8; ++j) b[j] = Bs[kk][tx * 8 + j];
#pragma unroll
            for (int i = 0; i < 4; ++i)
#pragma unroll
                for (int j = 0; j < 8; ++j)
                    acc[i][j] = fmaf(a[i], b[j], acc[i][j]);
        }
        __syncthreads();
    }

    float* outp = g_part + (size_t)s * BQ * DQ;
#pragma unroll
    for (int i = 0; i < 4; ++i) {
        const int m = m0 + ty * 4 + i;
#pragma unroll
        for (int j = 0; j < 8; ++j) {
            const int n = n0 + tx * 8 + j;
            if (n < DQ) outp[m * DQ + n] = acc[i][j];
        }
    }
}

// ---------------------------------------------------------------------------
// Reduce split-K partials + bias -> g_phi
// ---------------------------------------------------------------------------
__global__ void reduce_bias(const float* __restrict__ b2) {
    const int idx = blockIdx.x * blockDim.x + threadIdx.x;
    if (idx >= BQ * DQ) return;
    const int n = idx % DQ;
    float sum = b2[n];
#pragma unroll
    for (int p = 0; p < SPLITK; ++p) sum += g_part[p * (BQ * DQ) + idx];
    g_phi[idx] = sum;
}

// ---------------------------------------------------------------------------
// quad[b] = phi_b^T M_b phi_b, M = inv_Theta_11 (267 MB total -> HBM bound).
// One block per batch, per-lane (r,j)-partial accumulation, block reduce.
// ---------------------------------------------------------------------------
__global__ __launch_bounds__(256)
void quad_kernel(const float* __restrict__ M) {
    const int b = blockIdx.x;
    __shared__ float sphi[DQ];
    __shared__ float red[8];
    const int tid = threadIdx.x;
    for (int i = tid; i < DQ; i += 256) sphi[i] = g_phi[b * DQ + i];
    __syncthreads();

    const float* __restrict__ Mb = M + (size_t)b * DQ * DQ;
    const int lane = tid & 31, w = tid >> 5;
    float acc = 0.f;
    for (int r = w; r < DQ; r += 8) {
        const float pr = sphi[r];
        const float* __restrict__ row = Mb + (size_t)r * DQ;
        float rowsum = 0.f;
#pragma unroll 4
        for (int j = lane; j < DQ; j += 32)
            rowsum = fmaf(row[j], sphi[j], rowsum);
        acc = fmaf(pr, rowsum, acc);
    }
#pragma unroll
    for (int o = 16; o > 0; o >>= 1) acc += __shfl_xor_sync(0xffffffffu, acc, o);
    if (lane == 0) red[w] = acc;
    __syncthreads();
    if (tid == 0) {
        float s = 0.f;
#pragma unroll
        for (int i = 0; i < 8; ++i) s += red[i];
        g_quad[b] = s;
    }
}

// ---------------------------------------------------------------------------
// Final elementwise: phi_n = phi / sqrt(quad); soft-threshold with the
// tiny 1->5->1 MLP lambda.
// ---------------------------------------------------------------------------
__global__ void final_kernel(const float* __restrict__ sw1, const float* __restrict__ sb1,
                             const float* __restrict__ sw2, const float* __restrict__ sb2,
                             float* __restrict__ out) {
    const int idx = blockIdx.x * blockDim.x + threadIdx.x;
    if (idx >= BQ * DQ) return;
    const int b = idx / DQ;
    const float pn = g_phi[idx] / sqrtf(g_quad[b]);
    float lam = sb2[0];
#pragma unroll
    for (int i = 0; i < 5; ++i) {
        float g = fmaf(pn, sw1[i], sb1[i]);
        g = g > 0.f ? g : 0.f;
        lam = fmaf(g, sw2[i], lam);
    }
    lam = fabsf(lam) * 0.1f;
    float a = fabsf(pn) - lam;
    a = a > 0.f ? a : 0.f;
    out[idx] = copysignf(a, pn);
}

// ---------------------------------------------------------------------------
extern "C" void kernel_launch(void* const* d_in, const int* in_sizes, int n_in,
                              void* d_out, int out_size) {
    const float* theta12 = (const float*)d_in[0];
    // d_in[1] s_12, d_in[2] w_12, d_in[4] Theta, d_in[5] col : unused
    const float* invT    = (const float*)d_in[3];
    const float* w1      = (const float*)d_in[6];
    const float* b1      = (const float*)d_in[7];
    const float* w2      = (const float*)d_in[8];
    const float* b2      = (const float*)d_in[9];
    const float* sw1     = (const float*)d_in[10];
    const float* sb1     = (const float*)d_in[11];
    const float* sw2     = (const float*)d_in[12];
    const float* sb2     = (const float*)d_in[13];
    float* out = (float*)d_out;

    gemm1_relu<<<dim3(HQ / 128, BQ / 64), 256>>>(theta12, w1, b1);
    gemm2_split<<<dim3(4, BQ / 64, SPLITK), 256>>>(w2);
    reduce_bias<<<(BQ * DQ + 255) / 256, 256>>>(b2);
    quad_kernel<<<BQ, 256>>>(invT);
    final_kernel<<<(BQ * DQ + 255) / 256, 256>>>(sw1, sb1, sw2, sb2, out);
}

// round 5
// speedup vs baseline: 1.3651x; 1.3651x over previous
#include <cuda_runtime.h>
#include <math.h>

// Problem constants
#define BQ 256
#define DQ 511
#define HQ 5120
#define SPLITK 16
#define KCHUNK (HQ / SPLITK)   // 320
#define QSPLIT 8               // row-slices per batch for quad kernel
#define QROWS 64               // rows per slice (8*64 = 512 >= 511)

// Scratch (allocation-free rule: __device__ globals)
__device__ float g_h[BQ * HQ];                 // [256, 5120] hidden (post-ReLU)
__device__ float g_part[SPLITK * BQ * DQ];     // split-K partials
__device__ float g_phi[BQ * DQ];               // [256, 511]
__device__ float g_quadpart[BQ * QSPLIT];      // quad partials
__device__ float g_quad[BQ];                   // [256]

// ---------------------------------------------------------------------------
// GEMM1: g_h = relu(theta12[256,511] @ W1[5120,511]^T + b1)   (NT gemm)
// ---------------------------------------------------------------------------
__global__ __launch_bounds__(256, 2)
void gemm1_relu(const float* __restrict__ A, const float* __restrict__ W,
                const float* __restrict__ bias) {
    __shared__ float As[16][68];
    __shared__ float Bs[16][132];
    const int m0 = blockIdx.y * 64;
    const int n0 = blockIdx.x * 128;
    const int tid = threadIdx.x;
    const int lk = tid & 15, lr = tid >> 4;
    const int tx = tid & 15, ty = tid >> 4;

    float acc[4][8];
#pragma unroll
    for (int i = 0; i < 4; ++i)
#pragma unroll
        for (int j = 0; j < 8; ++j) acc[i][j] = 0.f;

    for (int k0 = 0; k0 < DQ; k0 += 16) {
        const int k = k0 + lk;
        const bool kin = (k < DQ);
#pragma unroll
        for (int i = 0; i < 4; ++i)
            As[lk][lr + i * 16] = kin ? A[(m0 + lr + i * 16) * DQ + k] : 0.f;
#pragma unroll
        for (int i = 0; i < 8; ++i)
            Bs[lk][lr + i * 16] = kin ? W[(n0 + lr + i * 16) * DQ + k] : 0.f;
        __syncthreads();
#pragma unroll
        for (int kk = 0; kk < 16; ++kk) {
            float a[4], b[8];
#pragma unroll
            for (int i = 0; i < 4; ++i) a[i] = As[kk][ty * 4 + i];
#pragma unroll
            for (int j = 0; j < 8; ++j) b[j] = Bs[kk][tx * 8 + j];
#pragma unroll
            for (int i = 0; i < 4; ++i)
#pragma unroll
                for (int j = 0; j < 8; ++j)
                    acc[i][j] = fmaf(a[i], b[j], acc[i][j]);
        }
        __syncthreads();
    }

#pragma unroll
    for (int i = 0; i < 4; ++i) {
        const int m = m0 + ty * 4 + i;
#pragma unroll
        for (int j = 0; j < 8; ++j) {
            const int n = n0 + tx * 8 + j;
            float v = acc[i][j] + bias[n];
            g_h[m * HQ + n] = v > 0.f ? v : 0.f;
        }
    }
}

// ---------------------------------------------------------------------------
// GEMM2 (split-K): g_part[s] = h[256,5120] @ W2[511,5120]^T over K-chunk s.
// ---------------------------------------------------------------------------
__global__ __launch_bounds__(256, 2)
void gemm2_split(const float* __restrict__ W2) {
    __shared__ float As[16][68];
    __shared__ float Bs[16][132];
    const int m0 = blockIdx.y * 64;
    const int n0 = blockIdx.x * 128;
    const int s  = blockIdx.z;
    const int tid = threadIdx.x;
    const int lk = tid & 15, lr = tid >> 4;
    const int tx = tid & 15, ty = tid >> 4;

    float acc[4][8];
#pragma unroll
    for (int i = 0; i < 4; ++i)
#pragma unroll
        for (int j = 0; j < 8; ++j) acc[i][j] = 0.f;

    const int kend = (s + 1) * KCHUNK;
    for (int k0 = s * KCHUNK; k0 < kend; k0 += 16) {
        const int k = k0 + lk;
#pragma unroll
        for (int i = 0; i < 4; ++i)
            As[lk][lr + i * 16] = g_h[(m0 + lr + i * 16) * HQ + k];
#pragma unroll
        for (int i = 0; i < 8; ++i) {
            const int n = n0 + lr + i * 16;
            Bs[lk][lr + i * 16] = (n < DQ) ? W2[n * HQ + k] : 0.f;
        }
        __syncthreads();
#pragma unroll
        for (int kk = 0; kk < 16; ++kk) {
            float a[4], b[8];
#pragma unroll
            for (int i = 0; i < 4; ++i) a[i] = As[kk][ty * 4 + i];
#pragma unroll
            for (int j = 0; j < 8; ++j) b[j] = Bs[kk][tx * 8 + j];
#pragma unroll
            for (int i = 0; i < 4; ++i)
#pragma unroll
                for (int j = 0; j < 8; ++j)
                    acc[i][j] = fmaf(a[i], b[j], acc[i][j]);
        }
        __syncthreads();
    }

    float* outp = g_part + (size_t)s * BQ * DQ;
#pragma unroll
    for (int i = 0; i < 4; ++i) {
        const int m = m0 + ty * 4 + i;
#pragma unroll
        for (int j = 0; j < 8; ++j) {
            const int n = n0 + tx * 8 + j;
            if (n < DQ) outp[m * DQ + n] = acc[i][j];
        }
    }
}

// ---------------------------------------------------------------------------
// Reduce split-K partials + bias -> g_phi
// ---------------------------------------------------------------------------
__global__ void reduce_bias(const float* __restrict__ b2) {
    const int idx = blockIdx.x * blockDim.x + threadIdx.x;
    if (idx >= BQ * DQ) return;
    const int n = idx % DQ;
    float sum = b2[n];
#pragma unroll
    for (int p = 0; p < SPLITK; ++p) sum += g_part[p * (BQ * DQ) + idx];
    g_phi[idx] = sum;
}

// ---------------------------------------------------------------------------
// quad partial: block (b, s) computes sum over rows [s*64, s*64+64) of
// phi_r * (M_b[r,:] . phi). 2048 blocks -> high occupancy -> HBM-bound.
// ---------------------------------------------------------------------------
__global__ __launch_bounds__(256)
void quad_kernel(const float* __restrict__ M) {
    const int b = blockIdx.x;
    const int s = blockIdx.y;
    __shared__ float sphi[DQ];
    __shared__ float red[8];
    const int tid = threadIdx.x;
    for (int i = tid; i < DQ; i += 256) sphi[i] = g_phi[b * DQ + i];
    __syncthreads();

    const float* __restrict__ Mb = M + (size_t)b * DQ * DQ;
    const int lane = tid & 31, w = tid >> 5;
    const int rend = min(DQ, (s + 1) * QROWS);
    float acc = 0.f;
    for (int r = s * QROWS + w; r < rend; r += 8) {
        const float pr = sphi[r];
        const float* __restrict__ row = Mb + (size_t)r * DQ;
        float rowsum = 0.f;
#pragma unroll 8
        for (int j = lane; j < DQ; j += 32)
            rowsum = fmaf(row[j], sphi[j], rowsum);
        acc = fmaf(pr, rowsum, acc);
    }
#pragma unroll
    for (int o = 16; o > 0; o >>= 1) acc += __shfl_xor_sync(0xffffffffu, acc, o);
    if (lane == 0) red[w] = acc;
    __syncthreads();
    if (tid == 0) {
        float sum = 0.f;
#pragma unroll
        for (int i = 0; i < 8; ++i) sum += red[i];
        g_quadpart[b * QSPLIT + s] = sum;
    }
}

// Fold the QSPLIT partials per batch.
__global__ void quad_sum() {
    const int b = threadIdx.x;  // 256 threads
    float sum = 0.f;
#pragma unroll
    for (int i = 0; i < QSPLIT; ++i) sum += g_quadpart[b * QSPLIT + i];
    g_quad[b] = sum;
}

// ---------------------------------------------------------------------------
// Final elementwise soft-threshold with the 1->5->1 MLP lambda.
// ---------------------------------------------------------------------------
__global__ void final_kernel(const float* __restrict__ sw1, const float* __restrict__ sb1,
                             const float* __restrict__ sw2, const float* __restrict__ sb2,
                             float* __restrict__ out) {
    const int idx = blockIdx.x * blockDim.x + threadIdx.x;
    if (idx >= BQ * DQ) return;
    const int b = idx / DQ;
    const float pn = g_phi[idx] / sqrtf(g_quad[b]);
    float lam = sb2[0];
#pragma unroll
    for (int i = 0; i < 5; ++i) {
        float g = fmaf(pn, sw1[i], sb1[i]);
        g = g > 0.f ? g : 0.f;
        lam = fmaf(g, sw2[i], lam);
    }
    lam = fabsf(lam) * 0.1f;
    float a = fabsf(pn) - lam;
    a = a > 0.f ? a : 0.f;
    out[idx] = copysignf(a, pn);
}

// ---------------------------------------------------------------------------
extern "C" void kernel_launch(void* const* d_in, const int* in_sizes, int n_in,
                              void* d_out, int out_size) {
    const float* theta12 = (const float*)d_in[0];
    const float* invT    = (const float*)d_in[3];
    const float* w1      = (const float*)d_in[6];
    const float* b1      = (const float*)d_in[7];
    const float* w2      = (const float*)d_in[8];
    const float* b2      = (const float*)d_in[9];
    const float* sw1     = (const float*)d_in[10];
    const float* sb1     = (const float*)d_in[11];
    const float* sw2     = (const float*)d_in[12];
    const float* sb2     = (const float*)d_in[13];
    float* out = (float*)d_out;

    gemm1_relu<<<dim3(HQ / 128, BQ / 64), 256>>>(theta12, w1, b1);
    gemm2_split<<<dim3(4, BQ / 64, SPLITK), 256>>>(w2);
    reduce_bias<<<(BQ * DQ + 255) / 256, 256>>>(b2);
    quad_kernel<<<dim3(BQ, QSPLIT), 256>>>(invT);
    quad_sum<<<1, 256>>>();
    final_kernel<<<(BQ * DQ + 255) / 256, 256>>>(sw1, sb1, sw2, sb2, out);
}

// round 6
// speedup vs baseline: 1.3658x; 1.0006x over previous
#include <cuda_runtime.h>
#include <math.h>

// Problem constants
#define BQ 256
#define DQ 511
#define HQ 5120
#define KP 512                 // padded K for GEMM1
#define SPLITK1 2              // GEMM1 k-split (chunks of 256)
#define SPLITK2 20             // GEMM2 k-split (chunks of 256)
#define KC 256                 // k-chunk (both gemms)
#define QSPLIT 8
#define QROWS 64

#define BM 64
#define BN 128
#define BK 16
#define NSTAGES (KC / BK)      // 16

// Scratch (allocation-free rule: __device__ globals)
__device__ __align__(16) float g_ap[BQ * KP];              // padded theta
__device__ __align__(16) float g_w1p[HQ * KP];             // padded W1
__device__ __align__(16) float g_part1[SPLITK1 * BQ * HQ]; // gemm1 partials
__device__ __align__(16) float g_h[BQ * HQ];               // hidden post-ReLU
__device__ __align__(16) float g_part2[SPLITK2 * BQ * DQ]; // gemm2 partials
__device__ __align__(16) float g_phi[BQ * DQ];
__device__ float g_quadpart[BQ * QSPLIT];
__device__ float g_quad[BQ];

// ---------------------------------------------------------------------------
// Padding copies (K=511 -> 512, zero fill)
// ---------------------------------------------------------------------------
__global__ void pad_a(const float* __restrict__ T) {
    const int idx = blockIdx.x * 256 + threadIdx.x;
    if (idx >= BQ * KP) return;
    const int r = idx >> 9, c = idx & 511;
    g_ap[idx] = (c < DQ) ? T[r * DQ + c] : 0.f;
}
__global__ void pad_w1(const float* __restrict__ W1) {
    const int idx = blockIdx.x * 256 + threadIdx.x;
    if (idx >= HQ * KP) return;
    const int r = idx >> 9, c = idx & 511;
    g_w1p[idx] = (c < DQ) ? W1[r * DQ + c] : 0.f;
}

// ---------------------------------------------------------------------------
// Shared compute macro: 64x128 tile, 256 threads, 4x8 per-thread.
// ---------------------------------------------------------------------------
#define GEMM_COMPUTE(st)                                                      \
    _Pragma("unroll")                                                         \
    for (int kk = 0; kk < BK; ++kk) {                                         \
        const float4 av = *(const float4*)&As[st][kk][ty * 4];                \
        const float4 b0 = *(const float4*)&Bs[st][kk][tx * 8];                \
        const float4 b1 = *(const float4*)&Bs[st][kk][tx * 8 + 4];            \
        const float a[4] = {av.x, av.y, av.z, av.w};                          \
        const float b[8] = {b0.x, b0.y, b0.z, b0.w, b1.x, b1.y, b1.z, b1.w};  \
        _Pragma("unroll")                                                     \
        for (int i = 0; i < 4; ++i)                                           \
            _Pragma("unroll")                                                 \
            for (int j = 0; j < 8; ++j)                                       \
                acc[i][j] = fmaf(a[i], b[j], acc[i][j]);                      \
    }

#define GEMM_STS(st)                                                          \
    As[st][ac + 0][arow] = ar.x;  As[st][ac + 1][arow] = ar.y;                \
    As[st][ac + 2][arow] = ar.z;  As[st][ac + 3][arow] = ar.w;                \
    Bs[st][bc + 0][brow] = br0.x; Bs[st][bc + 1][brow] = br0.y;               \
    Bs[st][bc + 2][brow] = br0.z; Bs[st][bc + 3][brow] = br0.w;               \
    Bs[st][bc + 4][brow] = br1.x; Bs[st][bc + 5][brow] = br1.y;               \
    Bs[st][bc + 6][brow] = br1.z; Bs[st][bc + 7][brow] = br1.w;

// ---------------------------------------------------------------------------
// GEMM1 (split-K=2): g_part1[z] = g_ap[256,512] @ g_w1p[5120,512]^T (k-chunk z)
// ---------------------------------------------------------------------------
__global__ __launch_bounds__(256, 2)
void gemm1_k() {
    __shared__ __align__(16) float As[2][BK][68];
    __shared__ __align__(16) float Bs[2][BK][132];
    const int n0 = blockIdx.x * BN;
    const int m0 = blockIdx.y * BM;
    const int kb = blockIdx.z * KC;
    const int tid = threadIdx.x;
    const int arow = tid >> 2, ac = (tid & 3) << 2;
    const int brow = tid >> 1, bc = (tid & 1) << 3;
    const int tx = tid & 15, ty = tid >> 4;

    const float* __restrict__ Ap = g_ap + (m0 + arow) * KP + kb + ac;
    const float* __restrict__ Bp = g_w1p + (size_t)(n0 + brow) * KP + kb + bc;

    float4 ar  = *(const float4*)Ap;
    float4 br0 = *(const float4*)Bp;
    float4 br1 = *(const float4*)(Bp + 4);

    float acc[4][8];
#pragma unroll
    for (int i = 0; i < 4; ++i)
#pragma unroll
        for (int j = 0; j < 8; ++j) acc[i][j] = 0.f;

    GEMM_STS(0)
    __syncthreads();

    int cur = 0;
#pragma unroll 1
    for (int s = 1; s < NSTAGES; ++s) {
        ar  = *(const float4*)(Ap + s * BK);
        br0 = *(const float4*)(Bp + s * BK);
        br1 = *(const float4*)(Bp + s * BK + 4);
        GEMM_COMPUTE(cur)
        const int nxt = cur ^ 1;
        GEMM_STS(nxt)
        __syncthreads();
        cur = nxt;
    }
    GEMM_COMPUTE(cur)

    float* __restrict__ o = g_part1 + (size_t)blockIdx.z * (BQ * HQ);
#pragma unroll
    for (int i = 0; i < 4; ++i) {
        const int m = m0 + ty * 4 + i;
        float4* orow = (float4*)(o + (size_t)m * HQ + n0 + tx * 8);
        orow[0] = make_float4(acc[i][0], acc[i][1], acc[i][2], acc[i][3]);
        orow[1] = make_float4(acc[i][4], acc[i][5], acc[i][6], acc[i][7]);
    }
}

// Reduce GEMM1 partials + bias + ReLU -> g_h (vectorized)
__global__ void reduce1(const float* __restrict__ b1) {
    const int i4 = blockIdx.x * 256 + threadIdx.x;
    if (i4 >= BQ * HQ / 4) return;
    const float4 p0 = ((const float4*)g_part1)[i4];
    const float4 p1 = ((const float4*)(g_part1 + BQ * HQ))[i4];
    const float4 bb = *(const float4*)&b1[(i4 * 4) % HQ];
    float4 v;
    v.x = fmaxf(p0.x + p1.x + bb.x, 0.f);
    v.y = fmaxf(p0.y + p1.y + bb.y, 0.f);
    v.z = fmaxf(p0.z + p1.z + bb.z, 0.f);
    v.w = fmaxf(p0.w + p1.w + bb.w, 0.f);
    ((float4*)g_h)[i4] = v;
}

// ---------------------------------------------------------------------------
// GEMM2 (split-K=20): g_part2[z] = g_h[256,5120] @ W2[511,5120]^T (k-chunk z)
// Rows n>=511 clamp to row 510 (their acc columns are never stored).
// ---------------------------------------------------------------------------
__global__ __launch_bounds__(256, 2)
void gemm2_k(const float* __restrict__ W2) {
    __shared__ __align__(16) float As[2][BK][68];
    __shared__ __align__(16) float Bs[2][BK][132];
    const int n0 = blockIdx.x * BN;
    const int m0 = blockIdx.y * BM;
    const int kb = blockIdx.z * KC;
    const int tid = threadIdx.x;
    const int arow = tid >> 2, ac = (tid & 3) << 2;
    const int brow = tid >> 1, bc = (tid & 1) << 3;
    const int tx = tid & 15, ty = tid >> 4;

    const int bn = min(n0 + brow, DQ - 1);
    const float* __restrict__ Ap = g_h + (m0 + arow) * HQ + kb + ac;
    const float* __restrict__ Bp = W2 + (size_t)bn * HQ + kb + bc;

    float4 ar  = *(const float4*)Ap;
    float4 br0 = *(const float4*)Bp;
    float4 br1 = *(const float4*)(Bp + 4);

    float acc[4][8];
#pragma unroll
    for (int i = 0; i < 4; ++i)
#pragma unroll
        for (int j = 0; j < 8; ++j) acc[i][j] = 0.f;

    GEMM_STS(0)
    __syncthreads();

    int cur = 0;
#pragma unroll 1
    for (int s = 1; s < NSTAGES; ++s) {
        ar  = *(const float4*)(Ap + s * BK);
        br0 = *(const float4*)(Bp + s * BK);
        br1 = *(const float4*)(Bp + s * BK + 4);
        GEMM_COMPUTE(cur)
        const int nxt = cur ^ 1;
        GEMM_STS(nxt)
        __syncthreads();
        cur = nxt;
    }
    GEMM_COMPUTE(cur)

    float* __restrict__ o = g_part2 + (size_t)blockIdx.z * (BQ * DQ);
#pragma unroll
    for (int i = 0; i < 4; ++i) {
        const int m = m0 + ty * 4 + i;
#pragma unroll
        for (int j = 0; j < 8; ++j) {
            const int n = n0 + tx * 8 + j;
            if (n < DQ) o[(size_t)m * DQ + n] = acc[i][j];
        }
    }
}

// Reduce GEMM2 partials + bias -> g_phi
__global__ void reduce2(const float* __restrict__ b2) {
    const int idx = blockIdx.x * 256 + threadIdx.x;
    if (idx >= BQ * DQ) return;
    const int n = idx % DQ;
    float sum = b2[n];
#pragma unroll
    for (int p = 0; p < SPLITK2; ++p) sum += g_part2[p * (BQ * DQ) + idx];
    g_phi[idx] = sum;
}

// ---------------------------------------------------------------------------
// Quadratic form partials (unchanged from R4: 2048 blocks, HBM-bound)
// ---------------------------------------------------------------------------
__global__ __launch_bounds__(256)
void quad_kernel(const float* __restrict__ M) {
    const int b = blockIdx.x;
    const int s = blockIdx.y;
    __shared__ float sphi[DQ];
    __shared__ float red[8];
    const int tid = threadIdx.x;
    for (int i = tid; i < DQ; i += 256) sphi[i] = g_phi[b * DQ + i];
    __syncthreads();

    const float* __restrict__ Mb = M + (size_t)b * DQ * DQ;
    const int lane = tid & 31, w = tid >> 5;
    const int rend = min(DQ, (s + 1) * QROWS);
    float acc = 0.f;
    for (int r = s * QROWS + w; r < rend; r += 8) {
        const float pr = sphi[r];
        const float* __restrict__ row = Mb + (size_t)r * DQ;
        float rowsum = 0.f;
#pragma unroll 8
        for (int j = lane; j < DQ; j += 32)
            rowsum = fmaf(row[j], sphi[j], rowsum);
        acc = fmaf(pr, rowsum, acc);
    }
#pragma unroll
    for (int o = 16; o > 0; o >>= 1) acc += __shfl_xor_sync(0xffffffffu, acc, o);
    if (lane == 0) red[w] = acc;
    __syncthreads();
    if (tid == 0) {
        float sum = 0.f;
#pragma unroll
        for (int i = 0; i < 8; ++i) sum += red[i];
        g_quadpart[b * QSPLIT + s] = sum;
    }
}

__global__ void quad_sum() {
    const int b = threadIdx.x;
    float sum = 0.f;
#pragma unroll
    for (int i = 0; i < QSPLIT; ++i) sum += g_quadpart[b * QSPLIT + i];
    g_quad[b] = sum;
}

// ---------------------------------------------------------------------------
// Final elementwise soft-threshold with the 1->5->1 MLP lambda.
// ---------------------------------------------------------------------------
__global__ void final_kernel(const float* __restrict__ sw1, const float* __restrict__ sb1,
                             const float* __restrict__ sw2, const float* __restrict__ sb2,
                             float* __restrict__ out) {
    const int idx = blockIdx.x * blockDim.x + threadIdx.x;
    if (idx >= BQ * DQ) return;
    const int b = idx / DQ;
    const float pn = g_phi[idx] / sqrtf(g_quad[b]);
    float lam = sb2[0];
#pragma unroll
    for (int i = 0; i < 5; ++i) {
        float g = fmaf(pn, sw1[i], sb1[i]);
        g = g > 0.f ? g : 0.f;
        lam = fmaf(g, sw2[i], lam);
    }
    lam = fabsf(lam) * 0.1f;
    float a = fabsf(pn) - lam;
    a = a > 0.f ? a : 0.f;
    out[idx] = copysignf(a, pn);
}

// ---------------------------------------------------------------------------
extern "C" void kernel_launch(void* const* d_in, const int* in_sizes, int n_in,
                              void* d_out, int out_size) {
    const float* theta12 = (const float*)d_in[0];
    const float* invT    = (const float*)d_in[3];
    const float* w1      = (const float*)d_in[6];
    const float* b1      = (const float*)d_in[7];
    const float* w2      = (const float*)d_in[8];
    const float* b2      = (const float*)d_in[9];
    const float* sw1     = (const float*)d_in[10];
    const float* sb1     = (const float*)d_in[11];
    const float* sw2     = (const float*)d_in[12];
    const float* sb2     = (const float*)d_in[13];
    float* out = (float*)d_out;

    pad_a <<<(BQ * KP + 255) / 256, 256>>>(theta12);
    pad_w1<<<(HQ * KP + 255) / 256, 256>>>(w1);
    gemm1_k<<<dim3(HQ / BN, BQ / BM, SPLITK1), 256>>>();
    reduce1<<<(BQ * HQ / 4 + 255) / 256, 256>>>(b1);
    gemm2_k<<<dim3((DQ + BN - 1) / BN, BQ / BM, SPLITK2), 256>>>(w2);
    reduce2<<<(BQ * DQ + 255) / 256, 256>>>(b2);
    quad_kernel<<<dim3(BQ, QSPLIT), 256>>>(invT);
    quad_sum<<<1, 256>>>();
    final_kernel<<<(BQ * DQ + 255) / 256, 256>>>(sw1, sb1, sw2, sb2, out);
}

// round 9
// speedup vs baseline: 2.1958x; 1.6077x over previous
#include <cuda_runtime.h>
#include <cuda_bf16.h>
#include <math.h>
#include <stdint.h>

// ---------------------------------------------------------------------------
// Problem constants
// ---------------------------------------------------------------------------
#define BQ 256
#define DQ 511
#define HQ 5120
#define KP1 512                // padded K for layer 1
#define KPACK1 (3 * KP1)       // 1536
#define KPACK2 (3 * HQ)        // 15360
#define NQ2 512                // padded N for layer 2
#define SPLITK2 15
#define STAGES1 (KPACK1 / 64)              // 24
#define STAGES2 (KPACK2 / (64 * SPLITK2))  // 16
#define KCHUNK2 (STAGES2 * 64)             // 1024
#define QSPLIT 8
#define QROWS 64

// ---------------------------------------------------------------------------
// Scratch (__device__ globals; no allocation allowed)
// ---------------------------------------------------------------------------
__device__ __align__(16) __nv_bfloat16 g_a1p[BQ * KPACK1];
__device__ __align__(16) __nv_bfloat16 g_b1p[(size_t)HQ * KPACK1];
__device__ __align__(16) float         g_h1[(size_t)BQ * HQ];          // [m][n]
__device__ __align__(16) __nv_bfloat16 g_a2p[(size_t)BQ * KPACK2];
__device__ __align__(16) __nv_bfloat16 g_b2p[(size_t)NQ2 * KPACK2];
__device__ __align__(16) float         g_p2[(size_t)SPLITK2 * BQ * NQ2]; // [z][m][n]
__device__ __align__(16) float         g_phi[BQ * DQ];
__device__ float g_quadpart[BQ * QSPLIT];
__device__ float g_quad[BQ];

#define SWZ(o) ((o) ^ (((o) >> 3) & 0x70))

__device__ __forceinline__ uint32_t smem_u32(const void* p) {
    uint32_t a;
    asm("{ .reg .u64 t; cvta.to.shared.u64 t, %1; cvt.u32.u64 %0, t; }"
        : "=r"(a) : "l"(p));
    return a;
}

// ---------------------------------------------------------------------------
// pack_split: fp32 -> bf16 hi/lo, K-concat 3 segments.
// isA: [hi|hi|lo]; else: [hi|lo|hi]. Rows >= vrows or cols >= K are zero.
// ---------------------------------------------------------------------------
__global__ void pack_split(const float* __restrict__ src, __nv_bfloat16* __restrict__ dst,
                           int nrows, int vrows, int K, int Kp, int isA) {
    const int idx = blockIdx.x * 256 + threadIdx.x;
    if (idx >= nrows * Kp) return;
    const int r = idx / Kp, c = idx - r * Kp;
    const float v = (r < vrows && c < K) ? src[(size_t)r * K + c] : 0.f;
    const __nv_bfloat16 hi = __float2bfloat16(v);
    const __nv_bfloat16 lo = __float2bfloat16(v - __bfloat162float(hi));
    const size_t base = (size_t)r * 3 * Kp;
    dst[base + c]          = hi;
    dst[base + Kp + c]     = isA ? hi : lo;
    dst[base + 2 * Kp + c] = isA ? lo : hi;
}

// ---------------------------------------------------------------------------
// gemm_mma: D[m][n] = sum_k A[m][k]*B[n][k], bf16 mma.sync m16n8k16.
// Block tile 128m x 64n x 64k, 8 warps (warp tile 32x32), double-buffered.
// Output m-major: out[z*zstride + m*out_ld + n].
// ---------------------------------------------------------------------------
__global__ __launch_bounds__(256, 2)
void gemm_mma(const __nv_bfloat16* __restrict__ A, const __nv_bfloat16* __restrict__ B,
              float* __restrict__ out, int kstride, int nstages, int out_ld,
              int kchunk, size_t zstride) {
    __shared__ __align__(1024) uint8_t smA[2][16384];   // 128 x 64 bf16, SW128
    __shared__ __align__(1024) uint8_t smB[2][8192];    // 64 x 64 bf16, SW128

    const int tid = threadIdx.x, l = tid & 31, wid = tid >> 5;
    const int wm = (wid & 3) * 32, wn = (wid >> 2) * 32;
    const int n0 = blockIdx.x * 64, m0 = blockIdx.y * 128;
    const size_t kbase = (size_t)blockIdx.z * kchunk;
    out += (size_t)blockIdx.z * zstride;

    const uint32_t sA0 = smem_u32(smA[0]), sA1 = smem_u32(smA[1]);
    const uint32_t sB0 = smem_u32(smB[0]), sB1 = smem_u32(smB[1]);

    // global load geometry
    const int arow = tid >> 3;                 // + 32*i
    const int ach  = (tid & 7) * 8;            // bf16 col
    const uint32_t a_sw = SWZ((uint32_t)(tid >> 3) * 128 + (uint32_t)(tid & 7) * 16);
    const uint32_t b_sw = a_sw;
    const __nv_bfloat16* Ag = A + (size_t)(m0 + arow) * kstride + kbase + ach;
    const __nv_bfloat16* Bg = B + (size_t)(n0 + arow) * kstride + kbase + ach;
    const size_t astep = (size_t)32 * kstride;

    // ldmatrix UNSWIZZLED byte offsets (swizzle applied per-kk with koff folded in)
    const uint32_t amat_u0 = (uint32_t)(wm + (l & 15)) * 128 + (uint32_t)(l >> 4) * 16;
    const uint32_t amat_u1 = amat_u0 + 16 * 128;
    const uint32_t bmat_u0 = (uint32_t)(wn + (l >> 4) * 8 + (l & 7)) * 128
                           + (uint32_t)((l >> 3) & 1) * 16;
    const uint32_t bmat_u1 = bmat_u0 + 16 * 128;

    float acc[2][4][4];
#pragma unroll
    for (int i = 0; i < 2; ++i)
#pragma unroll
        for (int j = 0; j < 4; ++j)
#pragma unroll
            for (int q = 0; q < 4; ++q) acc[i][j][q] = 0.f;

    uint4 pa[4], pb[2];

#define SWZ_R1 4096
#define SWZ_R2 8192
#define SWZ_R3 12288

#define LDG_STAGE(s)                                                        \
    {                                                                       \
        const __nv_bfloat16* ap = Ag + (size_t)(s) * 64;                    \
        const __nv_bfloat16* bp = Bg + (size_t)(s) * 64;                    \
        pa[0] = *(const uint4*)(ap);                                        \
        pa[1] = *(const uint4*)(ap + astep);                                \
        pa[2] = *(const uint4*)(ap + 2 * astep);                            \
        pa[3] = *(const uint4*)(ap + 3 * astep);                            \
        pb[0] = *(const uint4*)(bp);                                        \
        pb[1] = *(const uint4*)(bp + astep);                                \
    }

#define STS_STAGE(st)                                                       \
    {                                                                       \
        uint8_t* da = smA[st];                                              \
        uint8_t* db = smB[st];                                              \
        *(uint4*)(da + a_sw)          = pa[0];                              \
        *(uint4*)(da + a_sw + SWZ_R1) = pa[1];                              \
        *(uint4*)(da + a_sw + SWZ_R2) = pa[2];                              \
        *(uint4*)(da + a_sw + SWZ_R3) = pa[3];                              \
        *(uint4*)(db + b_sw)          = pb[0];                              \
        *(uint4*)(db + b_sw + SWZ_R1) = pb[1];                              \
    }

#define COMPUTE_STAGE(aS, bS)                                               \
    _Pragma("unroll")                                                       \
    for (int kk = 0; kk < 4; ++kk) {                                        \
        const uint32_t koff = (uint32_t)kk * 32; /* 16 bf16 = 32 bytes */   \
        uint32_t a0[4], a1[4], b0[4], b1[4];                                \
        asm volatile("ldmatrix.sync.aligned.m8n8.x4.shared.b16 {%0,%1,%2,%3}, [%4];" \
            : "=r"(a0[0]), "=r"(a0[1]), "=r"(a0[2]), "=r"(a0[3])            \
            : "r"((aS) + SWZ(amat_u0 + koff)));                             \
        asm volatile("ldmatrix.sync.aligned.m8n8.x4.shared.b16 {%0,%1,%2,%3}, [%4];" \
            : "=r"(a1[0]), "=r"(a1[1]), "=r"(a1[2]), "=r"(a1[3])            \
            : "r"((aS) + SWZ(amat_u1 + koff)));                             \
        asm volatile("ldmatrix.sync.aligned.m8n8.x4.shared.b16 {%0,%1,%2,%3}, [%4];" \
            : "=r"(b0[0]), "=r"(b0[1]), "=r"(b0[2]), "=r"(b0[3])            \
            : "r"((bS) + SWZ(bmat_u0 + koff)));                             \
        asm volatile("ldmatrix.sync.aligned.m8n8.x4.shared.b16 {%0,%1,%2,%3}, [%4];" \
            : "=r"(b1[0]), "=r"(b1[1]), "=r"(b1[2]), "=r"(b1[3])            \
            : "r"((bS) + SWZ(bmat_u1 + koff)));                             \
        _Pragma("unroll")                                                   \
        for (int mi = 0; mi < 2; ++mi) {                                    \
            const uint32_t* af = mi ? a1 : a0;                              \
            _Pragma("unroll")                                               \
            for (int ni = 0; ni < 4; ++ni) {                                \
                const uint32_t* bf = (ni < 2) ? b0 : b1;                    \
                const int w = (ni & 1) * 2;                                 \
                asm volatile(                                               \
                    "mma.sync.aligned.m16n8k16.row.col.f32.bf16.bf16.f32 "  \
                    "{%0,%1,%2,%3}, {%4,%5,%6,%7}, {%8,%9}, {%0,%1,%2,%3};" \
                    : "+f"(acc[mi][ni][0]), "+f"(acc[mi][ni][1]),           \
                      "+f"(acc[mi][ni][2]), "+f"(acc[mi][ni][3])            \
                    : "r"(af[0]), "r"(af[1]), "r"(af[2]), "r"(af[3]),       \
                      "r"(bf[w]), "r"(bf[w + 1]));                          \
            }                                                               \
        }                                                                   \
    }

    LDG_STAGE(0)
    STS_STAGE(0)
    __syncthreads();

    int cur = 0;
#pragma unroll 1
    for (int s = 1; s < nstages; ++s) {
        LDG_STAGE(s)
        if (cur == 0) { COMPUTE_STAGE(sA0, sB0) } else { COMPUTE_STAGE(sA1, sB1) }
        STS_STAGE(cur ^ 1)
        __syncthreads();
        cur ^= 1;
    }
    if (cur == 0) { COMPUTE_STAGE(sA0, sB0) } else { COMPUTE_STAGE(sA1, sB1) }

    // Epilogue: m-major float2 stores.
    const int me = m0 + wm + (l >> 2);
    const int ne = n0 + wn + (l & 3) * 2;
#pragma unroll
    for (int mi = 0; mi < 2; ++mi) {
#pragma unroll
        for (int ni = 0; ni < 4; ++ni) {
            const int m = me + mi * 16;
            const int n = ne + ni * 8;
            *(float2*)&out[(size_t)m * out_ld + n] =
                make_float2(acc[mi][ni][0], acc[mi][ni][1]);
            *(float2*)&out[(size_t)(m + 8) * out_ld + n] =
                make_float2(acc[mi][ni][2], acc[mi][ni][3]);
        }
    }
}

// ---------------------------------------------------------------------------
// pack_a2: g_h1[m][n] -> +bias -> relu -> bf16 split [hi|hi|lo] into g_a2p.
// ---------------------------------------------------------------------------
__global__ void pack_a2(const float* __restrict__ b1) {
    const int idx = blockIdx.x * 256 + threadIdx.x;
    if (idx >= BQ * HQ) return;
    const int m = idx / HQ, n = idx - m * HQ;
    const float v = fmaxf(g_h1[idx] + b1[n], 0.f);
    const __nv_bfloat16 hi = __float2bfloat16(v);
    const __nv_bfloat16 lo = __float2bfloat16(v - __bfloat162float(hi));
    const size_t base = (size_t)m * KPACK2;
    g_a2p[base + n]          = hi;
    g_a2p[base + HQ + n]     = hi;
    g_a2p[base + 2 * HQ + n] = lo;
}

// ---------------------------------------------------------------------------
// reduce2: sum split-K partials [z][m][512] + bias -> g_phi[m][511]
// ---------------------------------------------------------------------------
__global__ void reduce2(const float* __restrict__ b2) {
    const int idx = blockIdx.x * 256 + threadIdx.x;
    if (idx >= BQ * DQ) return;
    const int m = idx / DQ, n = idx - m * DQ;
    float s = b2[n];
#pragma unroll
    for (int z = 0; z < SPLITK2; ++z)
        s += g_p2[(size_t)z * BQ * NQ2 + (size_t)m * NQ2 + n];
    g_phi[idx] = s;
}

// ---------------------------------------------------------------------------
// Quadratic form partials (HBM-bound, 2048 blocks)
// ---------------------------------------------------------------------------
__global__ __launch_bounds__(256)
void quad_kernel(const float* __restrict__ M) {
    const int b = blockIdx.x;
    const int s = blockIdx.y;
    __shared__ float sphi[DQ];
    __shared__ float red[8];
    const int tid = threadIdx.x;
    for (int i = tid; i < DQ; i += 256) sphi[i] = g_phi[b * DQ + i];
    __syncthreads();

    const float* __restrict__ Mb = M + (size_t)b * DQ * DQ;
    const int lane = tid & 31, w = tid >> 5;
    const int rend = min(DQ, (s + 1) * QROWS);
    float acc = 0.f;
    for (int r = s * QROWS + w; r < rend; r += 8) {
        const float pr = sphi[r];
        const float* __restrict__ row = Mb + (size_t)r * DQ;
        float rowsum = 0.f;
#pragma unroll 8
        for (int j = lane; j < DQ; j += 32)
            rowsum = fmaf(row[j], sphi[j], rowsum);
        acc = fmaf(pr, rowsum, acc);
    }
#pragma unroll
    for (int o = 16; o > 0; o >>= 1) acc += __shfl_xor_sync(0xffffffffu, acc, o);
    if (lane == 0) red[w] = acc;
    __syncthreads();
    if (tid == 0) {
        float sum = 0.f;
#pragma unroll
        for (int i = 0; i < 8; ++i) sum += red[i];
        g_quadpart[b * QSPLIT + s] = sum;
    }
}

__global__ void quad_sum() {
    const int b = threadIdx.x;
    float sum = 0.f;
#pragma unroll
    for (int i = 0; i < QSPLIT; ++i) sum += g_quadpart[b * QSPLIT + i];
    g_quad[b] = sum;
}

// ---------------------------------------------------------------------------
// Final elementwise soft-threshold with the 1->5->1 MLP lambda.
// ---------------------------------------------------------------------------
__global__ void final_kernel(const float* __restrict__ sw1, const float* __restrict__ sb1,
                             const float* __restrict__ sw2, const float* __restrict__ sb2,
                             float* __restrict__ out) {
    const int idx = blockIdx.x * blockDim.x + threadIdx.x;
    if (idx >= BQ * DQ) return;
    const int b = idx / DQ;
    const float pn = g_phi[idx] / sqrtf(g_quad[b]);
    float lam = sb2[0];
#pragma unroll
    for (int i = 0; i < 5; ++i) {
        float g = fmaf(pn, sw1[i], sb1[i]);
        g = g > 0.f ? g : 0.f;
        lam = fmaf(g, sw2[i], lam);
    }
    lam = fabsf(lam) * 0.1f;
    float a = fabsf(pn) - lam;
    a = a > 0.f ? a : 0.f;
    out[idx] = copysignf(a, pn);
}

// ---------------------------------------------------------------------------
extern "C" void kernel_launch(void* const* d_in, const int* in_sizes, int n_in,
                              void* d_out, int out_size) {
    const float* theta12 = (const float*)d_in[0];
    const float* invT    = (const float*)d_in[3];
    const float* w1      = (const float*)d_in[6];
    const float* b1      = (const float*)d_in[7];
    const float* w2      = (const float*)d_in[8];
    const float* b2      = (const float*)d_in[9];
    const float* sw1     = (const float*)d_in[10];
    const float* sb1     = (const float*)d_in[11];
    const float* sw2     = (const float*)d_in[12];
    const float* sb2     = (const float*)d_in[13];
    float* out = (float*)d_out;

    __nv_bfloat16 *a1p, *b1p, *a2p, *b2p;
    float *h1, *p2;
    cudaGetSymbolAddress((void**)&a1p, g_a1p);
    cudaGetSymbolAddress((void**)&b1p, g_b1p);
    cudaGetSymbolAddress((void**)&a2p, g_a2p);
    cudaGetSymbolAddress((void**)&b2p, g_b2p);
    cudaGetSymbolAddress((void**)&h1,  g_h1);
    cudaGetSymbolAddress((void**)&p2,  g_p2);

    // Layer-1 packs: A [hi|hi|lo], B [hi|lo|hi], K 511 -> 512 padded
    pack_split<<<(BQ * KP1 + 255) / 256, 256>>>(theta12, a1p, BQ, BQ, DQ, KP1, 1);
    pack_split<<<(HQ * KP1 + 255) / 256, 256>>>(w1, b1p, HQ, HQ, DQ, KP1, 0);
    // GEMM1: h1[256][5120] = a1p[256,1536] @ b1p[5120,1536]^T
    gemm_mma<<<dim3(HQ / 64, BQ / 128, 1), 256>>>(a1p, b1p, h1, KPACK1, STAGES1, HQ, 0, 0);
    // bias + relu + split -> a2p
    pack_a2<<<(BQ * HQ + 255) / 256, 256>>>(b1);
    // W2 pack (rows padded 511 -> 512)
    pack_split<<<(NQ2 * HQ + 255) / 256, 256>>>(w2, b2p, NQ2, DQ, HQ, HQ, 0);
    // GEMM2: split-K=15, partials [z][m][512]
    gemm_mma<<<dim3(NQ2 / 64, BQ / 128, SPLITK2), 256>>>(a2p, b2p, p2, KPACK2, STAGES2, NQ2,
                                                         KCHUNK2, (size_t)BQ * NQ2);
    reduce2<<<(BQ * DQ + 255) / 256, 256>>>(b2);

    quad_kernel<<<dim3(BQ, QSPLIT), 256>>>(invT);
    quad_sum<<<1, 256>>>();
    final_kernel<<<(BQ * DQ + 255) / 256, 256>>>(sw1, sb1, sw2, sb2, out);
}

// round 12
// speedup vs baseline: 2.2250x; 1.0133x over previous
#include <cuda_runtime.h>
#include <cuda_bf16.h>
#include <math.h>
#include <stdint.h>

// ---------------------------------------------------------------------------
// Problem constants
// ---------------------------------------------------------------------------
#define BQ 256
#define DQ 511
#define HQ 5120
#define KP1 512                 // padded K, layer 1
#define NQ2 512                 // padded N, layer 2
#define SPLITK1 2
#define SPLITK2 16
#define SPP1 (KP1 / SPLITK1 / 64)   // 4 stages per pass (gemm1)
#define SPP2 (HQ / SPLITK2 / 64)    // 5 stages per pass (gemm2)
#define QSPLIT 8
#define QROWS 64

// ---------------------------------------------------------------------------
// Scratch (__device__ globals; no allocation allowed). Packed layout: [hi|lo].
// ---------------------------------------------------------------------------
__device__ __align__(16) __nv_bfloat16 g_a1p[BQ * 2 * KP1];
__device__ __align__(16) __nv_bfloat16 g_b1p[(size_t)HQ * 2 * KP1];
__device__ __align__(16) float         g_p1[(size_t)SPLITK1 * BQ * HQ];   // [z][m][n]
__device__ __align__(16) __nv_bfloat16 g_a2p[(size_t)BQ * 2 * HQ];
__device__ __align__(16) __nv_bfloat16 g_b2p[(size_t)NQ2 * 2 * HQ];
__device__ __align__(16) float         g_p2[(size_t)SPLITK2 * BQ * NQ2];  // [z][m][n]
__device__ __align__(16) float         g_phi[BQ * DQ];
__device__ float g_quadpart[BQ * QSPLIT];

#define SWZ(o) ((o) ^ (((o) >> 3) & 0x70))

__device__ __forceinline__ uint32_t smem_u32(const void* p) {
    uint32_t a;
    asm("{ .reg .u64 t; cvta.to.shared.u64 t, %1; cvt.u32.u64 %0, t; }"
        : "=r"(a) : "l"(p));
    return a;
}

// ---------------------------------------------------------------------------
// pack_split: fp32 -> [hi|lo] bf16 segments, 8 elems/thread, 16B stores.
// ---------------------------------------------------------------------------
__global__ void pack_split(const float* __restrict__ src, __nv_bfloat16* __restrict__ dst,
                           int nrows, int vrows, int K, int Kp) {
    const int n8 = Kp >> 3;
    const int idx = blockIdx.x * 256 + threadIdx.x;
    if (idx >= nrows * n8) return;
    const int r = idx / n8, c8 = (idx - r * n8) << 3;

    __align__(16) __nv_bfloat16 hb[8], lb[8];
#pragma unroll
    for (int t = 0; t < 8; ++t) {
        const int c = c8 + t;
        const float v = (r < vrows && c < K) ? src[(size_t)r * K + c] : 0.f;
        hb[t] = __float2bfloat16(v);
        lb[t] = __float2bfloat16(v - __bfloat162float(hb[t]));
    }
    const size_t base = (size_t)r * 2 * Kp;
    *(uint4*)&dst[base + c8]      = *(uint4*)hb;
    *(uint4*)&dst[base + Kp + c8] = *(uint4*)lb;
}

// ---------------------------------------------------------------------------
// gemm_mma: D[m][n] = sum_k A[m][k]*B[n][k] with bf16-split 3-pass schedule:
//   pass0 Ah*Bh, pass1 Ah*Bl, pass2 Al*Bh   (A,B stored [hi|lo], seg len Kp)
// Block tile 128m x 64n x 64k, 8 warps, double-buffered smem.
// Split-K: z covers [z*zchunk, z*zchunk+spp*64) of each pass segment.
// Output m-major: out[z*zstride + m*out_ld + n].
// ---------------------------------------------------------------------------
__global__ __launch_bounds__(256, 2)
void gemm_mma(const __nv_bfloat16* __restrict__ A, const __nv_bfloat16* __restrict__ B,
              float* __restrict__ out, int kstride, int Kp, int spp,
              int zchunk, int out_ld, size_t zstride) {
    __shared__ __align__(1024) uint8_t smA[2][16384];   // 128 x 64 bf16, SW128
    __shared__ __align__(1024) uint8_t smB[2][8192];    // 64 x 64 bf16, SW128

    const int tid = threadIdx.x, l = tid & 31, wid = tid >> 5;
    const int wm = (wid & 3) * 32, wn = (wid >> 2) * 32;
    const int n0 = blockIdx.x * 64, m0 = blockIdx.y * 128;
    const int kz = blockIdx.z * zchunk;
    const int nst = 3 * spp;
    out += (size_t)blockIdx.z * zstride;

    const uint32_t sA0 = smem_u32(smA[0]), sA1 = smem_u32(smA[1]);
    const uint32_t sB0 = smem_u32(smB[0]), sB1 = smem_u32(smB[1]);

    const int arow = tid >> 3;
    const int ach  = (tid & 7) * 8;
    const uint32_t a_sw = SWZ((uint32_t)(tid >> 3) * 128 + (uint32_t)(tid & 7) * 16);
    const uint32_t b_sw = a_sw;
    const __nv_bfloat16* Ag = A + (size_t)(m0 + arow) * kstride + ach;
    const __nv_bfloat16* Bg = B + (size_t)(n0 + arow) * kstride + ach;
    const size_t astep = (size_t)32 * kstride;

    const uint32_t amat_u0 = (uint32_t)(wm + (l & 15)) * 128 + (uint32_t)(l >> 4) * 16;
    const uint32_t amat_u1 = amat_u0 + 16 * 128;
    const uint32_t bmat_u0 = (uint32_t)(wn + (l >> 4) * 8 + (l & 7)) * 128
                           + (uint32_t)((l >> 3) & 1) * 16;
    const uint32_t bmat_u1 = bmat_u0 + 16 * 128;

    float acc[2][4][4];
#pragma unroll
    for (int i = 0; i < 2; ++i)
#pragma unroll
        for (int j = 0; j < 4; ++j)
#pragma unroll
            for (int q = 0; q < 4; ++q) acc[i][j][q] = 0.f;

    uint4 pa[4], pb[2];

#define SWZ_R1 4096
#define SWZ_R2 8192
#define SWZ_R3 12288

#define KAPOS(s, p, i) (((p) == 2 ? Kp : 0) + kz + (i) * 64)
#define KBPOS(s, p, i) (((p) == 1 ? Kp : 0) + kz + (i) * 64)

#define LDG_STAGE(kA, kB)                                                   \
    {                                                                       \
        const __nv_bfloat16* ap = Ag + (kA);                                \
        const __nv_bfloat16* bp = Bg + (kB);                                \
        pa[0] = *(const uint4*)(ap);                                        \
        pa[1] = *(const uint4*)(ap + astep);                                \
        pa[2] = *(const uint4*)(ap + 2 * astep);                            \
        pa[3] = *(const uint4*)(ap + 3 * astep);                            \
        pb[0] = *(const uint4*)(bp);                                        \
        pb[1] = *(const uint4*)(bp + astep);                                \
    }

#define STS_STAGE(st)                                                       \
    {                                                                       \
        uint8_t* da = smA[st];                                              \
        uint8_t* db = smB[st];                                              \
        *(uint4*)(da + a_sw)          = pa[0];                              \
        *(uint4*)(da + a_sw + SWZ_R1) = pa[1];                              \
        *(uint4*)(da + a_sw + SWZ_R2) = pa[2];                              \
        *(uint4*)(da + a_sw + SWZ_R3) = pa[3];                              \
        *(uint4*)(db + b_sw)          = pb[0];                              \
        *(uint4*)(db + b_sw + SWZ_R1) = pb[1];                              \
    }

#define COMPUTE_STAGE(aS, bS)                                               \
    _Pragma("unroll")                                                       \
    for (int kk = 0; kk < 4; ++kk) {                                        \
        const uint32_t koff = (uint32_t)kk * 32;                            \
        uint32_t a0[4], a1[4], b0[4], b1[4];                                \
        asm volatile("ldmatrix.sync.aligned.m8n8.x4.shared.b16 {%0,%1,%2,%3}, [%4];" \
            : "=r"(a0[0]), "=r"(a0[1]), "=r"(a0[2]), "=r"(a0[3])            \
            : "r"((aS) + SWZ(amat_u0 + koff)));                             \
        asm volatile("ldmatrix.sync.aligned.m8n8.x4.shared.b16 {%0,%1,%2,%3}, [%4];" \
            : "=r"(a1[0]), "=r"(a1[1]), "=r"(a1[2]), "=r"(a1[3])            \
            : "r"((aS) + SWZ(amat_u1 + koff)));                             \
        asm volatile("ldmatrix.sync.aligned.m8n8.x4.shared.b16 {%0,%1,%2,%3}, [%4];" \
            : "=r"(b0[0]), "=r"(b0[1]), "=r"(b0[2]), "=r"(b0[3])            \
            : "r"((bS) + SWZ(bmat_u0 + koff)));                             \
        asm volatile("ldmatrix.sync.aligned.m8n8.x4.shared.b16 {%0,%1,%2,%3}, [%4];" \
            : "=r"(b1[0]), "=r"(b1[1]), "=r"(b1[2]), "=r"(b1[3])            \
            : "r"((bS) + SWZ(bmat_u1 + koff)));                             \
        _Pragma("unroll")                                                   \
        for (int mi = 0; mi < 2; ++mi) {                                    \
            const uint32_t* af = mi ? a1 : a0;                              \
            _Pragma("unroll")                                               \
            for (int ni = 0; ni < 4; ++ni) {                                \
                const uint32_t* bf = (ni < 2) ? b0 : b1;                    \
                const int w = (ni & 1) * 2;                                 \
                asm volatile(                                               \
                    "mma.sync.aligned.m16n8k16.row.col.f32.bf16.bf16.f32 "  \
                    "{%0,%1,%2,%3}, {%4,%5,%6,%7}, {%8,%9}, {%0,%1,%2,%3};" \
                    : "+f"(acc[mi][ni][0]), "+f"(acc[mi][ni][1]),           \
                      "+f"(acc[mi][ni][2]), "+f"(acc[mi][ni][3])            \
                    : "r"(af[0]), "r"(af[1]), "r"(af[2]), "r"(af[3]),       \
                      "r"(bf[w]), "r"(bf[w + 1]));                          \
            }                                                               \
        }                                                                   \
    }

    LDG_STAGE(KAPOS(0, 0, 0), KBPOS(0, 0, 0))
    STS_STAGE(0)
    __syncthreads();

    int cur = 0;
#pragma unroll 1
    for (int s = 1; s < nst; ++s) {
        const int p = s / spp, i = s - p * spp;
        LDG_STAGE(KAPOS(s, p, i), KBPOS(s, p, i))
        if (cur == 0) { COMPUTE_STAGE(sA0, sB0) } else { COMPUTE_STAGE(sA1, sB1) }
        STS_STAGE(cur ^ 1)
        __syncthreads();
        cur ^= 1;
    }
    if (cur == 0) { COMPUTE_STAGE(sA0, sB0) } else { COMPUTE_STAGE(sA1, sB1) }

    // Epilogue: m-major float2 stores.
    const int me = m0 + wm + (l >> 2);
    const int ne = n0 + wn + (l & 3) * 2;
#pragma unroll
    for (int mi = 0; mi < 2; ++mi) {
#pragma unroll
        for (int ni = 0; ni < 4; ++ni) {
            const int m = me + mi * 16;
            const int n = ne + ni * 8;
            *(float2*)&out[(size_t)m * out_ld + n] =
                make_float2(acc[mi][ni][0], acc[mi][ni][1]);
            *(float2*)&out[(size_t)(m + 8) * out_ld + n] =
                make_float2(acc[mi][ni][2], acc[mi][ni][3]);
        }
    }
}

// ---------------------------------------------------------------------------
// pack_a2: sum gemm1 split-K partials + bias -> relu -> [hi|lo] bf16, 16B IO.
// ---------------------------------------------------------------------------
__global__ void pack_a2(const float* __restrict__ b1) {
    const int n8 = HQ >> 3;
    const int idx = blockIdx.x * 256 + threadIdx.x;
    if (idx >= BQ * n8) return;
    const int m = idx / n8, c8 = (idx - m * n8) << 3;
    const size_t o = (size_t)m * HQ + c8;

    const float4 v0 = *(const float4*)&g_p1[o];
    const float4 v1 = *(const float4*)&g_p1[o + 4];
    const float4 u0 = *(const float4*)&g_p1[(size_t)BQ * HQ + o];
    const float4 u1 = *(const float4*)&g_p1[(size_t)BQ * HQ + o + 4];
    const float4 c0 = *(const float4*)&b1[c8];
    const float4 c1 = *(const float4*)&b1[c8 + 4];

    float v[8] = {
        fmaxf(v0.x + u0.x + c0.x, 0.f), fmaxf(v0.y + u0.y + c0.y, 0.f),
        fmaxf(v0.z + u0.z + c0.z, 0.f), fmaxf(v0.w + u0.w + c0.w, 0.f),
        fmaxf(v1.x + u1.x + c1.x, 0.f), fmaxf(v1.y + u1.y + c1.y, 0.f),
        fmaxf(v1.z + u1.z + c1.z, 0.f), fmaxf(v1.w + u1.w + c1.w, 0.f)};

    __align__(16) __nv_bfloat16 hb[8], lb[8];
#pragma unroll
    for (int t = 0; t < 8; ++t) {
        hb[t] = __float2bfloat16(v[t]);
        lb[t] = __float2bfloat16(v[t] - __bfloat162float(hb[t]));
    }
    const size_t base = (size_t)m * 2 * HQ;
    *(uint4*)&g_a2p[base + c8]      = *(uint4*)hb;
    *(uint4*)&g_a2p[base + HQ + c8] = *(uint4*)lb;
}

// ---------------------------------------------------------------------------
// reduce2: sum gemm2 split-K partials [z][m][512] + bias -> g_phi[m][511]
// ---------------------------------------------------------------------------
__global__ void reduce2(const float* __restrict__ b2) {
    const int idx = blockIdx.x * 256 + threadIdx.x;
    if (idx >= BQ * DQ) return;
    const int m = idx / DQ, n = idx - m * DQ;
    float s = b2[n];
#pragma unroll
    for (int z = 0; z < SPLITK2; ++z)
        s += g_p2[(size_t)z * BQ * NQ2 + (size_t)m * NQ2 + n];
    g_phi[idx] = s;
}

// ---------------------------------------------------------------------------
// quad_kernel: float4 rows + 4 pre-shifted phi copies in smem.
// Block (b, s) covers rows [s*64, s*64+64); 2048 blocks, HBM-bound.
// ---------------------------------------------------------------------------
__global__ __launch_bounds__(256)
void quad_kernel(const float* __restrict__ M) {
    const int b = blockIdx.x;
    const int s = blockIdx.y;
    __shared__ float sphi[512];
    __shared__ __align__(16) float sh[4][512];   // sh[c][x] = phi[x + c]
    __shared__ float red[8];
    const int tid = threadIdx.x;

    for (int i = tid; i < 512; i += 256) {
        const float v = (i < DQ) ? g_phi[b * DQ + i] : 0.f;
        sphi[i] = v;
    }
    __syncthreads();
    for (int x = tid; x < 512; x += 256) {
#pragma unroll
        for (int c = 0; c < 4; ++c) {
            const int ix = x + c;
            sh[c][x] = (ix < DQ) ? sphi[ix] : 0.f;
        }
    }
    __syncthreads();

    const float* __restrict__ Mb = M + (size_t)b * DQ * DQ;
    const int lane = tid & 31, w = tid >> 5;
    const int rend = min(DQ, (s + 1) * QROWS);
    float acc = 0.f;

    for (int r = s * QROWS + w; r < rend; r += 8) {
        const float* __restrict__ row = Mb + (size_t)r * DQ;
        const uint32_t mis = (uint32_t)(uintptr_t)row & 15u;
        const int peel = mis ? (int)((16u - mis) >> 2) : 0;   // 0..3

        float rs0 = 0.f, rs1 = 0.f;
        if (lane < peel) rs0 = row[lane] * sphi[lane];

        const float4* __restrict__ rv = (const float4*)(row + peel);
        const float* __restrict__ shp = sh[peel];
#pragma unroll 4
        for (int j = lane; j < 127; j += 32) {
            const float4 v  = rv[j];
            const float4 sp = *(const float4*)&shp[4 * j];
            rs0 = fmaf(v.x, sp.x, rs0);
            rs1 = fmaf(v.y, sp.y, rs1);
            rs0 = fmaf(v.z, sp.z, rs0);
            rs1 = fmaf(v.w, sp.w, rs1);
        }
        const int tail0 = peel + 508;
        if (lane < DQ - tail0)
            rs1 = fmaf(row[tail0 + lane], sphi[tail0 + lane], rs1);

        acc = fmaf(sphi[r], rs0 + rs1, acc);
    }

#pragma unroll
    for (int o = 16; o > 0; o >>= 1) acc += __shfl_xor_sync(0xffffffffu, acc, o);
    if (lane == 0) red[w] = acc;
    __syncthreads();
    if (tid == 0) {
        float sum = 0.f;
#pragma unroll
        for (int i = 0; i < 8; ++i) sum += red[i];
        g_quadpart[b * QSPLIT + s] = sum;
    }
}

// ---------------------------------------------------------------------------
// Final elementwise: inline quad-partial sum + soft-threshold (1->5->1 MLP).
// ---------------------------------------------------------------------------
__global__ void final_kernel(const float* __restrict__ sw1, const float* __restrict__ sb1,
                             const float* __restrict__ sw2, const float* __restrict__ sb2,
                             float* __restrict__ out) {
    const int idx = blockIdx.x * blockDim.x + threadIdx.x;
    if (idx >= BQ * DQ) return;
    const int b = idx / DQ;
    float q = 0.f;
#pragma unroll
    for (int i = 0; i < QSPLIT; ++i) q += g_quadpart[b * QSPLIT + i];
    const float pn = g_phi[idx] / sqrtf(q);
    float lam = sb2[0];
#pragma unroll
    for (int i = 0; i < 5; ++i) {
        float g = fmaf(pn, sw1[i], sb1[i]);
        g = g > 0.f ? g : 0.f;
        lam = fmaf(g, sw2[i], lam);
    }
    lam = fabsf(lam) * 0.1f;
    float a = fabsf(pn) - lam;
    a = a > 0.f ? a : 0.f;
    out[idx] = copysignf(a, pn);
}

// ---------------------------------------------------------------------------
extern "C" void kernel_launch(void* const* d_in, const int* in_sizes, int n_in,
                              void* d_out, int out_size) {
    const float* theta12 = (const float*)d_in[0];
    const float* invT    = (const float*)d_in[3];
    const float* w1      = (const float*)d_in[6];
    const float* b1      = (const float*)d_in[7];
    const float* w2      = (const float*)d_in[8];
    const float* b2      = (const float*)d_in[9];
    const float* sw1     = (const float*)d_in[10];
    const float* sb1     = (const float*)d_in[11];
    const float* sw2     = (const float*)d_in[12];
    const float* sb2     = (const float*)d_in[13];
    float* out = (float*)d_out;

    __nv_bfloat16 *a1p, *b1p, *a2p, *b2p;
    float *p1, *p2;
    cudaGetSymbolAddress((void**)&a1p, g_a1p);
    cudaGetSymbolAddress((void**)&b1p, g_b1p);
    cudaGetSymbolAddress((void**)&a2p, g_a2p);
    cudaGetSymbolAddress((void**)&b2p, g_b2p);
    cudaGetSymbolAddress((void**)&p1,  g_p1);
    cudaGetSymbolAddress((void**)&p2,  g_p2);

    // Layer-1 packs ([hi|lo], K 511 -> 512 padded)
    pack_split<<<(BQ * KP1 / 8 + 255) / 256, 256>>>(theta12, a1p, BQ, BQ, DQ, KP1);
    pack_split<<<(HQ * KP1 / 8 + 255) / 256, 256>>>(w1, b1p, HQ, HQ, DQ, KP1);
    // GEMM1: split-K=2, 3-pass bf16-split; out p1 [z][m][5120]
    gemm_mma<<<dim3(HQ / 64, BQ / 128, SPLITK1), 256>>>(
        a1p, b1p, p1, 2 * KP1, KP1, SPP1, KP1 / SPLITK1, HQ, (size_t)BQ * HQ);
    // bias + relu + [hi|lo] split -> a2p
    pack_a2<<<(BQ * HQ / 8 + 255) / 256, 256>>>(b1);
    // W2 pack (rows padded 511 -> 512)
    pack_split<<<(NQ2 * HQ / 8 + 255) / 256, 256>>>(w2, b2p, NQ2, DQ, HQ, HQ);
    // GEMM2: split-K=16, 3-pass; out p2 [z][m][512]
    gemm_mma<<<dim3(NQ2 / 64, BQ / 128, SPLITK2), 256>>>(
        a2p, b2p, p2, 2 * HQ, HQ, SPP2, HQ / SPLITK2, NQ2, (size_t)BQ * NQ2);
    reduce2<<<(BQ * DQ + 255) / 256, 256>>>(b2);

    quad_kernel<<<dim3(BQ, QSPLIT), 256>>>(invT);
    final_kernel<<<(BQ * DQ + 255) / 256, 256>>>(sw1, sb1, sw2, sb2, out);
}

// round 13
// speedup vs baseline: 2.9107x; 1.3082x over previous
#include <cuda_runtime.h>
#include <cuda_bf16.h>
#include <math.h>
#include <stdint.h>

// ---------------------------------------------------------------------------
// Problem constants
// ---------------------------------------------------------------------------
#define BQ 256
#define DQ 511
#define HQ 5120
#define KP1 512                 // padded K, layer 1
#define NQ2 512                 // padded N, layer 2
#define SPLITK1 2
#define SPLITK2 16
#define SPP1 (KP1 / SPLITK1 / 64)   // 4 stages per pass (gemm1)
#define SPP2 (HQ / SPLITK2 / 64)    // 5 stages per pass (gemm2)
#define QSPLIT 8

// ---------------------------------------------------------------------------
// Scratch (__device__ globals; no allocation allowed). Packed layout: [hi|lo].
// ---------------------------------------------------------------------------
__device__ __align__(16) __nv_bfloat16 g_a1p[BQ * 2 * KP1];
__device__ __align__(16) __nv_bfloat16 g_b1p[(size_t)HQ * 2 * KP1];
__device__ __align__(16) float         g_p1[(size_t)SPLITK1 * BQ * HQ];   // [z][m][n]
__device__ __align__(16) __nv_bfloat16 g_a2p[(size_t)BQ * 2 * HQ];
__device__ __align__(16) __nv_bfloat16 g_b2p[(size_t)NQ2 * 2 * HQ];
__device__ __align__(16) float         g_p2[(size_t)SPLITK2 * BQ * NQ2];  // [z][m][n]
__device__ __align__(16) float         g_phi[BQ * DQ];
__device__ float g_quadpart[BQ * QSPLIT];

#define SWZ(o) ((o) ^ (((o) >> 3) & 0x70))

__device__ __forceinline__ uint32_t smem_u32(const void* p) {
    uint32_t a;
    asm("{ .reg .u64 t; cvta.to.shared.u64 t, %1; cvt.u32.u64 %0, t; }"
        : "=r"(a) : "l"(p));
    return a;
}

// ---------------------------------------------------------------------------
// pack_split: fp32 -> [hi|lo] bf16 segments, 8 elems/thread, 16B stores.
// ---------------------------------------------------------------------------
__global__ void pack_split(const float* __restrict__ src, __nv_bfloat16* __restrict__ dst,
                           int nrows, int vrows, int K, int Kp) {
    const int n8 = Kp >> 3;
    const int idx = blockIdx.x * 256 + threadIdx.x;
    if (idx >= nrows * n8) return;
    const int r = idx / n8, c8 = (idx - r * n8) << 3;

    __align__(16) __nv_bfloat16 hb[8], lb[8];
#pragma unroll
    for (int t = 0; t < 8; ++t) {
        const int c = c8 + t;
        const float v = (r < vrows && c < K) ? src[(size_t)r * K + c] : 0.f;
        hb[t] = __float2bfloat16(v);
        lb[t] = __float2bfloat16(v - __bfloat162float(hb[t]));
    }
    const size_t base = (size_t)r * 2 * Kp;
    *(uint4*)&dst[base + c8]      = *(uint4*)hb;
    *(uint4*)&dst[base + Kp + c8] = *(uint4*)lb;
}

// ---------------------------------------------------------------------------
// gemm_mma: D[m][n] = sum_k A[m][k]*B[n][k] with bf16-split 3-pass schedule:
//   pass0 Ah*Bh, pass1 Ah*Bl, pass2 Al*Bh   (A,B stored [hi|lo], seg len Kp)
// Block tile 128m x 64n x 64k, 8 warps, double-buffered smem.
// ---------------------------------------------------------------------------
__global__ __launch_bounds__(256, 2)
void gemm_mma(const __nv_bfloat16* __restrict__ A, const __nv_bfloat16* __restrict__ B,
              float* __restrict__ out, int kstride, int Kp, int spp,
              int zchunk, int out_ld, size_t zstride) {
    __shared__ __align__(1024) uint8_t smA[2][16384];   // 128 x 64 bf16, SW128
    __shared__ __align__(1024) uint8_t smB[2][8192];    // 64 x 64 bf16, SW128

    const int tid = threadIdx.x, l = tid & 31, wid = tid >> 5;
    const int wm = (wid & 3) * 32, wn = (wid >> 2) * 32;
    const int n0 = blockIdx.x * 64, m0 = blockIdx.y * 128;
    const int kz = blockIdx.z * zchunk;
    const int nst = 3 * spp;
    out += (size_t)blockIdx.z * zstride;

    const uint32_t sA0 = smem_u32(smA[0]), sA1 = smem_u32(smA[1]);
    const uint32_t sB0 = smem_u32(smB[0]), sB1 = smem_u32(smB[1]);

    const int arow = tid >> 3;
    const int ach  = (tid & 7) * 8;
    const uint32_t a_sw = SWZ((uint32_t)(tid >> 3) * 128 + (uint32_t)(tid & 7) * 16);
    const uint32_t b_sw = a_sw;
    const __nv_bfloat16* Ag = A + (size_t)(m0 + arow) * kstride + ach;
    const __nv_bfloat16* Bg = B + (size_t)(n0 + arow) * kstride + ach;
    const size_t astep = (size_t)32 * kstride;

    const uint32_t amat_u0 = (uint32_t)(wm + (l & 15)) * 128 + (uint32_t)(l >> 4) * 16;
    const uint32_t amat_u1 = amat_u0 + 16 * 128;
    const uint32_t bmat_u0 = (uint32_t)(wn + (l >> 4) * 8 + (l & 7)) * 128
                           + (uint32_t)((l >> 3) & 1) * 16;
    const uint32_t bmat_u1 = bmat_u0 + 16 * 128;

    float acc[2][4][4];
#pragma unroll
    for (int i = 0; i < 2; ++i)
#pragma unroll
        for (int j = 0; j < 4; ++j)
#pragma unroll
            for (int q = 0; q < 4; ++q) acc[i][j][q] = 0.f;

    uint4 pa[4], pb[2];

#define SWZ_R1 4096
#define SWZ_R2 8192
#define SWZ_R3 12288

#define KAPOS(s, p, i) (((p) == 2 ? Kp : 0) + kz + (i) * 64)
#define KBPOS(s, p, i) (((p) == 1 ? Kp : 0) + kz + (i) * 64)

#define LDG_STAGE(kA, kB)                                                   \
    {                                                                       \
        const __nv_bfloat16* ap = Ag + (kA);                                \
        const __nv_bfloat16* bp = Bg + (kB);                                \
        pa[0] = *(const uint4*)(ap);                                        \
        pa[1] = *(const uint4*)(ap + astep);                                \
        pa[2] = *(const uint4*)(ap + 2 * astep);                            \
        pa[3] = *(const uint4*)(ap + 3 * astep);                            \
        pb[0] = *(const uint4*)(bp);                                        \
        pb[1] = *(const uint4*)(bp + astep);                                \
    }

#define STS_STAGE(st)                                                       \
    {                                                                       \
        uint8_t* da = smA[st];                                              \
        uint8_t* db = smB[st];                                              \
        *(uint4*)(da + a_sw)          = pa[0];                              \
        *(uint4*)(da + a_sw + SWZ_R1) = pa[1];                              \
        *(uint4*)(da + a_sw + SWZ_R2) = pa[2];                              \
        *(uint4*)(da + a_sw + SWZ_R3) = pa[3];                              \
        *(uint4*)(db + b_sw)          = pb[0];                              \
        *(uint4*)(db + b_sw + SWZ_R1) = pb[1];                              \
    }

#define COMPUTE_STAGE(aS, bS)                                               \
    _Pragma("unroll")                                                       \
    for (int kk = 0; kk < 4; ++kk) {                                        \
        const uint32_t koff = (uint32_t)kk * 32;                            \
        uint32_t a0[4], a1[4], b0[4], b1[4];                                \
        asm volatile("ldmatrix.sync.aligned.m8n8.x4.shared.b16 {%0,%1,%2,%3}, [%4];" \
            : "=r"(a0[0]), "=r"(a0[1]), "=r"(a0[2]), "=r"(a0[3])            \
            : "r"((aS) + SWZ(amat_u0 + koff)));                             \
        asm volatile("ldmatrix.sync.aligned.m8n8.x4.shared.b16 {%0,%1,%2,%3}, [%4];" \
            : "=r"(a1[0]), "=r"(a1[1]), "=r"(a1[2]), "=r"(a1[3])            \
            : "r"((aS) + SWZ(amat_u1 + koff)));                             \
        asm volatile("ldmatrix.sync.aligned.m8n8.x4.shared.b16 {%0,%1,%2,%3}, [%4];" \
            : "=r"(b0[0]), "=r"(b0[1]), "=r"(b0[2]), "=r"(b0[3])            \
            : "r"((bS) + SWZ(bmat_u0 + koff)));                             \
        asm volatile("ldmatrix.sync.aligned.m8n8.x4.shared.b16 {%0,%1,%2,%3}, [%4];" \
            : "=r"(b1[0]), "=r"(b1[1]), "=r"(b1[2]), "=r"(b1[3])            \
            : "r"((bS) + SWZ(bmat_u1 + koff)));                             \
        _Pragma("unroll")                                                   \
        for (int mi = 0; mi < 2; ++mi) {                                    \
            const uint32_t* af = mi ? a1 : a0;                              \
            _Pragma("unroll")                                               \
            for (int ni = 0; ni < 4; ++ni) {                                \
                const uint32_t* bf = (ni < 2) ? b0 : b1;                    \
                const int w = (ni & 1) * 2;                                 \
                asm volatile(                                               \
                    "mma.sync.aligned.m16n8k16.row.col.f32.bf16.bf16.f32 "  \
                    "{%0,%1,%2,%3}, {%4,%5,%6,%7}, {%8,%9}, {%0,%1,%2,%3};" \
                    : "+f"(acc[mi][ni][0]), "+f"(acc[mi][ni][1]),           \
                      "+f"(acc[mi][ni][2]), "+f"(acc[mi][ni][3])            \
                    : "r"(af[0]), "r"(af[1]), "r"(af[2]), "r"(af[3]),       \
                      "r"(bf[w]), "r"(bf[w + 1]));                          \
            }                                                               \
        }                                                                   \
    }

    LDG_STAGE(KAPOS(0, 0, 0), KBPOS(0, 0, 0))
    STS_STAGE(0)
    __syncthreads();

    int cur = 0;
#pragma unroll 1
    for (int s = 1; s < nst; ++s) {
        const int p = s / spp, i = s - p * spp;
        LDG_STAGE(KAPOS(s, p, i), KBPOS(s, p, i))
        if (cur == 0) { COMPUTE_STAGE(sA0, sB0) } else { COMPUTE_STAGE(sA1, sB1) }
        STS_STAGE(cur ^ 1)
        __syncthreads();
        cur ^= 1;
    }
    if (cur == 0) { COMPUTE_STAGE(sA0, sB0) } else { COMPUTE_STAGE(sA1, sB1) }

    // Epilogue: m-major float2 stores.
    const int me = m0 + wm + (l >> 2);
    const int ne = n0 + wn + (l & 3) * 2;
#pragma unroll
    for (int mi = 0; mi < 2; ++mi) {
#pragma unroll
        for (int ni = 0; ni < 4; ++ni) {
            const int m = me + mi * 16;
            const int n = ne + ni * 8;
            *(float2*)&out[(size_t)m * out_ld + n] =
                make_float2(acc[mi][ni][0], acc[mi][ni][1]);
            *(float2*)&out[(size_t)(m + 8) * out_ld + n] =
                make_float2(acc[mi][ni][2], acc[mi][ni][3]);
        }
    }
}

// ---------------------------------------------------------------------------
// pack_a2: sum gemm1 split-K partials + bias -> relu -> [hi|lo] bf16, 16B IO.
// ---------------------------------------------------------------------------
__global__ void pack_a2(const float* __restrict__ b1) {
    const int n8 = HQ >> 3;
    const int idx = blockIdx.x * 256 + threadIdx.x;
    if (idx >= BQ * n8) return;
    const int m = idx / n8, c8 = (idx - m * n8) << 3;
    const size_t o = (size_t)m * HQ + c8;

    const float4 v0 = *(const float4*)&g_p1[o];
    const float4 v1 = *(const float4*)&g_p1[o + 4];
    const float4 u0 = *(const float4*)&g_p1[(size_t)BQ * HQ + o];
    const float4 u1 = *(const float4*)&g_p1[(size_t)BQ * HQ + o + 4];
    const float4 c0 = *(const float4*)&b1[c8];
    const float4 c1 = *(const float4*)&b1[c8 + 4];

    float v[8] = {
        fmaxf(v0.x + u0.x + c0.x, 0.f), fmaxf(v0.y + u0.y + c0.y, 0.f),
        fmaxf(v0.z + u0.z + c0.z, 0.f), fmaxf(v0.w + u0.w + c0.w, 0.f),
        fmaxf(v1.x + u1.x + c1.x, 0.f), fmaxf(v1.y + u1.y + c1.y, 0.f),
        fmaxf(v1.z + u1.z + c1.z, 0.f), fmaxf(v1.w + u1.w + c1.w, 0.f)};

    __align__(16) __nv_bfloat16 hb[8], lb[8];
#pragma unroll
    for (int t = 0; t < 8; ++t) {
        hb[t] = __float2bfloat16(v[t]);
        lb[t] = __float2bfloat16(v[t] - __bfloat162float(hb[t]));
    }
    const size_t base = (size_t)m * 2 * HQ;
    *(uint4*)&g_a2p[base + c8]      = *(uint4*)hb;
    *(uint4*)&g_a2p[base + HQ + c8] = *(uint4*)lb;
}

// ---------------------------------------------------------------------------
// reduce2: sum gemm2 split-K partials [z][m][512] + bias -> g_phi[m][511]
// ---------------------------------------------------------------------------
__global__ void reduce2(const float* __restrict__ b2) {
    const int idx = blockIdx.x * 256 + threadIdx.x;
    if (idx >= BQ * DQ) return;
    const int m = idx / DQ, n = idx - m * DQ;
    float s = b2[n];
#pragma unroll
    for (int z = 0; z < SPLITK2; ++z)
        s += g_p2[(size_t)z * BQ * NQ2 + (size_t)m * NQ2 + n];
    g_phi[idx] = s;
}

// ---------------------------------------------------------------------------
// quad_kernel (SYMMETRIC, upper-triangular):
//   quad = sum_r phi_r * (2 * sum_{j>=r} M_rj phi_j  -  M_rr phi_r)
// M is bitwise-symmetric (A A^T / D + I), so only the upper triangle is read:
// 134 MB instead of 267 MB. Load balance: pair row r (len 511-r) with row
// 510-r (len r+1) -> every pair costs exactly 512 elements. Block (b, s)
// covers pairs r = s*32 .. s*32+31; warp w takes pairs i == w (mod 8).
// Self-pair r = 255 is processed once.
// ---------------------------------------------------------------------------
__global__ __launch_bounds__(256)
void quad_kernel(const float* __restrict__ M) {
    const int b = blockIdx.x;
    const int s = blockIdx.y;
    __shared__ float sphi[512];
    __shared__ float red[8];
    const int tid = threadIdx.x;
    const int lane = tid & 31, w = tid >> 5;

    for (int i = tid; i < 512; i += 256)
        sphi[i] = (i < DQ) ? g_phi[b * DQ + i] : 0.f;
    __syncthreads();

    const float* __restrict__ Mb = M + (size_t)b * DQ * DQ;
    float acc = 0.f;

#pragma unroll 1
    for (int i = w; i < 32; i += 8) {
        const int r1 = s * 32 + i;        // 0..255
        const int r2 = 510 - r1;          // 255..510

        // row r1, columns j in [r1, 511)
        {
            const float* __restrict__ row = Mb + (size_t)r1 * DQ;
            float rs = 0.f;
#pragma unroll 4
            for (int j = r1 + lane; j < DQ; j += 32)
                rs = fmaf(row[j], sphi[j], rs);
            acc = fmaf(sphi[r1], 2.f * rs, acc);
            if (lane == 0)
                acc -= sphi[r1] * row[r1] * sphi[r1];
        }
        // row r2, columns j in [r2, 511)  (skip if self-pair)
        if (r2 != r1) {
            const float* __restrict__ row = Mb + (size_t)r2 * DQ;
            float rs = 0.f;
#pragma unroll 4
            for (int j = r2 + lane; j < DQ; j += 32)
                rs = fmaf(row[j], sphi[j], rs);
            acc = fmaf(sphi[r2], 2.f * rs, acc);
            if (lane == 0)
                acc -= sphi[r2] * row[r2] * sphi[r2];
        }
    }

#pragma unroll
    for (int o = 16; o > 0; o >>= 1) acc += __shfl_xor_sync(0xffffffffu, acc, o);
    if (lane == 0) red[w] = acc;
    __syncthreads();
    if (tid == 0) {
        float sum = 0.f;
#pragma unroll
        for (int i = 0; i < 8; ++i) sum += red[i];
        g_quadpart[b * QSPLIT + s] = sum;
    }
}

// ---------------------------------------------------------------------------
// Final elementwise: inline quad-partial sum + soft-threshold (1->5->1 MLP).
// ---------------------------------------------------------------------------
__global__ void final_kernel(const float* __restrict__ sw1, const float* __restrict__ sb1,
                             const float* __restrict__ sw2, const float* __restrict__ sb2,
                             float* __restrict__ out) {
    const int idx = blockIdx.x * blockDim.x + threadIdx.x;
    if (idx >= BQ * DQ) return;
    const int b = idx / DQ;
    float q = 0.f;
#pragma unroll
    for (int i = 0; i < QSPLIT; ++i) q += g_quadpart[b * QSPLIT + i];
    const float pn = g_phi[idx] / sqrtf(q);
    float lam = sb2[0];
#pragma unroll
    for (int i = 0; i < 5; ++i) {
        float g = fmaf(pn, sw1[i], sb1[i]);
        g = g > 0.f ? g : 0.f;
        lam = fmaf(g, sw2[i], lam);
    }
    lam = fabsf(lam) * 0.1f;
    float a = fabsf(pn) - lam;
    a = a > 0.f ? a : 0.f;
    out[idx] = copysignf(a, pn);
}

// ---------------------------------------------------------------------------
extern "C" void kernel_launch(void* const* d_in, const int* in_sizes, int n_in,
                              void* d_out, int out_size) {
    const float* theta12 = (const float*)d_in[0];
    const float* invT    = (const float*)d_in[3];
    const float* w1      = (const float*)d_in[6];
    const float* b1      = (const float*)d_in[7];
    const float* w2      = (const float*)d_in[8];
    const float* b2      = (const float*)d_in[9];
    const float* sw1     = (const float*)d_in[10];
    const float* sb1     = (const float*)d_in[11];
    const float* sw2     = (const float*)d_in[12];
    const float* sb2     = (const float*)d_in[13];
    float* out = (float*)d_out;

    __nv_bfloat16 *a1p, *b1p, *a2p, *b2p;
    float *p1, *p2;
    cudaGetSymbolAddress((void**)&a1p, g_a1p);
    cudaGetSymbolAddress((void**)&b1p, g_b1p);
    cudaGetSymbolAddress((void**)&a2p, g_a2p);
    cudaGetSymbolAddress((void**)&b2p, g_b2p);
    cudaGetSymbolAddress((void**)&p1,  g_p1);
    cudaGetSymbolAddress((void**)&p2,  g_p2);

    // Layer-1 packs ([hi|lo], K 511 -> 512 padded)
    pack_split<<<(BQ * KP1 / 8 + 255) / 256, 256>>>(theta12, a1p, BQ, BQ, DQ, KP1);
    pack_split<<<(HQ * KP1 / 8 + 255) / 256, 256>>>(w1, b1p, HQ, HQ, DQ, KP1);
    // GEMM1: split-K=2, 3-pass bf16-split; out p1 [z][m][5120]
    gemm_mma<<<dim3(HQ / 64, BQ / 128, SPLITK1), 256>>>(
        a1p, b1p, p1, 2 * KP1, KP1, SPP1, KP1 / SPLITK1, HQ, (size_t)BQ * HQ);
    // bias + relu + [hi|lo] split -> a2p
    pack_a2<<<(BQ * HQ / 8 + 255) / 256, 256>>>(b1);
    // W2 pack (rows padded 511 -> 512)
    pack_split<<<(NQ2 * HQ / 8 + 255) / 256, 256>>>(w2, b2p, NQ2, DQ, HQ, HQ);
    // GEMM2: split-K=16, 3-pass; out p2 [z][m][512]
    gemm_mma<<<dim3(NQ2 / 64, BQ / 128, SPLITK2), 256>>>(
        a2p, b2p, p2, 2 * HQ, HQ, SPP2, HQ / SPLITK2, NQ2, (size_t)BQ * NQ2);
    reduce2<<<(BQ * DQ + 255) / 256, 256>>>(b2);

    quad_kernel<<<dim3(BQ, QSPLIT), 256>>>(invT);
    final_kernel<<<(BQ * DQ + 255) / 256, 256>>>(sw1, sb1, sw2, sb2, out);
}